// round 13
// baseline (speedup 1.0000x reference)
#include <cuda_runtime.h>
#include <math.h>

#define NN 4096
#define DIMF 256
#define HIDF 64
#define NHEAD 4
#define NCLS 16
#define JSPLIT 2

// ---------------- scratch (device globals; no allocation) ----------------
__device__ float g_h1[NN * DIMF];              // layer-1 features [i][h*64+d]
__device__ float g_f1a[NHEAD * NN];            // f1 per head [h][i]
__device__ float g_f2a[NHEAD * NN];            // f2 per head [h][i]
__device__ float g_pacc[JSPLIT * NN * DIMF];   // partial attention accumulators
__device__ float g_pss[JSPLIT * NHEAD * NN];   // partial softmax denominators [js][h][i]
__device__ float g_hcat[NN * DIMF];            // after attention + ELU
__device__ float g_h2[NN * NCLS];              // layer-2 features
__device__ float g_f1b[NN];
__device__ float g_f2b[NN];

// ---------------- fast exp: FFMA/ALU only, no MUFU ----------------
__device__ __forceinline__ float fast_exp(float z) {
    z = fminf(fmaxf(z, -80.0f), 80.0f);
    float t  = z * 1.4426950408889634f;
    float tf = t + 12582912.0f;
    float fn = tf - 12582912.0f;
    float r  = t - fn;
    int   n  = __float_as_int(tf) - 0x4B400000;
    float scale = __int_as_float((n + 127) << 23);
    float p;
    p = 1.5401354e-4f;
    p = fmaf(p, r, 1.3333558e-3f);
    p = fmaf(p, r, 9.6181291e-3f);
    p = fmaf(p, r, 5.5504109e-2f);
    p = fmaf(p, r, 2.4022651e-1f);
    p = fmaf(p, r, 6.9314718e-1f);
    p = fmaf(p, r, 1.0f);
    return p * scale;
}

// ---------------- tf32 mma helpers ----------------
__device__ __forceinline__ unsigned cvt_tf32(float x) {
    unsigned r;
    asm("cvt.rna.tf32.f32 %0, %1;" : "=r"(r) : "f"(x));
    return r;
}
__device__ __forceinline__ void mma_tf32(float& c0, float& c1, float& c2, float& c3,
                                         unsigned a0, unsigned a1, unsigned a2, unsigned a3,
                                         unsigned b0, unsigned b1) {
    asm("mma.sync.aligned.m16n8k8.row.col.f32.tf32.tf32.f32 "
        "{%0,%1,%2,%3}, {%4,%5,%6,%7}, {%8,%9}, {%0,%1,%2,%3};"
        : "+f"(c0), "+f"(c1), "+f"(c2), "+f"(c3)
        : "r"(a0), "r"(a1), "r"(a2), "r"(a3), "r"(b0), "r"(b1));
}

// ---------------- K1: h1 = x @ W1^T ----------------
__global__ void k1_gemm(const float* __restrict__ A, const float* __restrict__ W) {
    __shared__ __align__(16) float As[16][68];
    __shared__ __align__(16) float Bs[16][68];
    int t = threadIdx.x;
    int tx = t & 15, ty = t >> 4;
    int bm = blockIdx.x * 64;
    int bn = blockIdx.y * 64;

    float acc[4][4];
#pragma unroll
    for (int i = 0; i < 4; i++)
#pragma unroll
        for (int j = 0; j < 4; j++) acc[i][j] = 0.f;

    int lr = t >> 2;
    int lk = (t & 3) * 4;

    for (int k0 = 0; k0 < DIMF; k0 += 16) {
        float4 av = *(const float4*)(A + (bm + lr) * DIMF + k0 + lk);
        float4 bv = *(const float4*)(W + (bn + lr) * DIMF + k0 + lk);
        As[lk + 0][lr] = av.x; As[lk + 1][lr] = av.y;
        As[lk + 2][lr] = av.z; As[lk + 3][lr] = av.w;
        Bs[lk + 0][lr] = bv.x; Bs[lk + 1][lr] = bv.y;
        Bs[lk + 2][lr] = bv.z; Bs[lk + 3][lr] = bv.w;
        __syncthreads();
#pragma unroll
        for (int k = 0; k < 16; k++) {
            float4 a4 = *(const float4*)&As[k][ty * 4];
            float4 b4 = *(const float4*)&Bs[k][tx * 4];
            float a[4] = {a4.x, a4.y, a4.z, a4.w};
            float b[4] = {b4.x, b4.y, b4.z, b4.w};
#pragma unroll
            for (int i = 0; i < 4; i++)
#pragma unroll
                for (int j = 0; j < 4; j++) acc[i][j] += a[i] * b[j];
        }
        __syncthreads();
    }
#pragma unroll
    for (int i = 0; i < 4; i++) {
        float4 o = make_float4(acc[i][0], acc[i][1], acc[i][2], acc[i][3]);
        *(float4*)&g_h1[(bm + ty * 4 + i) * DIMF + bn + tx * 4] = o;
    }
}

// ---------------- K2a/K2b: f1 / f2 per head (split so k3 is launch #4) ----
__global__ void k2a_f1(const float* __restrict__ a1) {
    __shared__ float s1[256];
    int i = blockIdx.x;
    int t = threadIdx.x;
    s1[t] = g_h1[i * DIMF + t] * a1[t];
    __syncthreads();
    for (int st = 32; st > 0; st >>= 1) {
        if ((t & 63) < st) s1[t] += s1[t + st];
        __syncthreads();
    }
    if ((t & 63) == 0) g_f1a[(t >> 6) * NN + i] = s1[t];
}
__global__ void k2b_f2(const float* __restrict__ a2) {
    __shared__ float s2[256];
    int i = blockIdx.x;
    int t = threadIdx.x;
    s2[t] = g_h1[i * DIMF + t] * a2[t];
    __syncthreads();
    for (int st = 32; st > 0; st >>= 1) {
        if ((t & 63) < st) s2[t] += s2[t + st];
        __syncthreads();
    }
    if ((t & 63) == 0) g_f2a[(t >> 6) * NN + i] = s2[t];
}

// ---------------- K3: layer-1 attention with tf32 tensor-core MMA ----------
// grid (NN/R1, JSPLIT), 256 threads (8 warps). Per chunk:
//   exp phase -> P[4 heads][16 r][64 jj] (tf32 bits in smem)
//   MMA phase -> out[16][256] += P_head @ H[64 x 256] via m16n8k8.tf32
// Warp w covers d in [32w, 32w+32), head = w>>1.
#define R1 16
#define CH1 64
#define JCHUNKS (NN / JSPLIT / CH1)   // 32
__global__ void k3_attn1(const int* __restrict__ adj) {
    __shared__ float f1s[R1][NHEAD];
    __shared__ int   adjs[R1][CH1];
    __shared__ float f2s[NHEAD][CH1];
    __shared__ unsigned psu[NHEAD][R1][68];   // tf32 bits, stride 68 (banks: 68%32=4)

    int t = threadIdx.x;
    int i0 = blockIdx.x * R1;
    int js = blockIdx.y;
    int jbase = js * (NN / JSPLIT);

    if (t < R1 * NHEAD) {
        int r = t >> 2, h = t & 3;
        f1s[r][h] = g_f1a[h * NN + i0 + r];
    }

    const int jj   = t & 63;
    const int hh   = t >> 6;
    const int w    = t >> 5;          // warp id 0..7
    const int lane = t & 31;
    const int gid  = lane >> 2;       // 0..7
    const int tig  = lane & 3;        // 0..3
    const int head = w >> 1;
    const int dbase = w * 32;

    float acc[4][4];                  // [nt][c0..c3]
#pragma unroll
    for (int nt = 0; nt < 4; nt++)
#pragma unroll
        for (int c = 0; c < 4; c++) acc[nt][c] = 0.f;

    float sacc[R1];
#pragma unroll
    for (int r = 0; r < R1; r++) sacc[r] = 0.f;

    for (int c = 0; c < JCHUNKS; c++) {
        int j0 = jbase + c * CH1;
        __syncthreads();
        // adjacency chunk 16x64
#pragma unroll
        for (int u = 0; u < 4; u++) {
            int idx = t + u * 256;
            int r = idx >> 6, j2 = idx & 63;
            adjs[r][j2] = adj[(i0 + r) * NN + j0 + j2];
        }
        // f2 chunk 4x64
        f2s[hh][jj] = g_f2a[hh * NN + j0 + jj];
        __syncthreads();
        // exp phase: p in f32 (denominator), tf32 bits to smem (numerator)
        {
            float f2v = f2s[hh][jj];
#pragma unroll
            for (int r = 0; r < R1; r++) {
                float z = f1s[r][hh] + f2v;
                float e = z > 0.f ? z : 0.01f * z;
                float pv = fast_exp(e);
                float p = (adjs[r][jj] != 0 && e != 0.f) ? pv : 0.f;
                psu[hh][r][jj] = cvt_tf32(p);
                sacc[r] += p;
            }
        }
        __syncthreads();
        // MMA phase: A fragments from psu, B from gmem (g_h1, tf32-converted)
        unsigned af[8][4];
#pragma unroll
        for (int kt = 0; kt < 8; kt++) {
            int col = kt * 8 + tig;
            af[kt][0] = psu[head][gid][col];
            af[kt][1] = psu[head][gid + 8][col];
            af[kt][2] = psu[head][gid][col + 4];
            af[kt][3] = psu[head][gid + 8][col + 4];
        }
#pragma unroll
        for (int nt = 0; nt < 4; nt++) {
            int dcol = dbase + nt * 8 + gid;
#pragma unroll
            for (int kt = 0; kt < 8; kt++) {
                int krow = j0 + kt * 8 + tig;
                unsigned b0 = cvt_tf32(__ldg(&g_h1[krow * DIMF + dcol]));
                unsigned b1 = cvt_tf32(__ldg(&g_h1[(krow + 4) * DIMF + dcol]));
                mma_tf32(acc[nt][0], acc[nt][1], acc[nt][2], acc[nt][3],
                         af[kt][0], af[kt][1], af[kt][2], af[kt][3], b0, b1);
            }
        }
    }

    // store accumulators: C[r][col]: c0/c1 at row gid, c2/c3 at row gid+8
#pragma unroll
    for (int nt = 0; nt < 4; nt++) {
        int col = dbase + nt * 8 + tig * 2;
        float2 lohi0 = make_float2(acc[nt][0], acc[nt][1]);
        float2 lohi1 = make_float2(acc[nt][2], acc[nt][3]);
        *(float2*)&g_pacc[(size_t)js * NN * DIMF + (i0 + gid) * DIMF + col]     = lohi0;
        *(float2*)&g_pacc[(size_t)js * NN * DIMF + (i0 + gid + 8) * DIMF + col] = lohi1;
    }

    // reduce sacc over the 64 jj-lanes per head (reuse psu storage as float scratch)
    __syncthreads();
    float* scr = (float*)psu;   // 4*16*68 = 4352 >= 4096 needed
#pragma unroll
    for (int r = 0; r < R1; r++) scr[t * 16 + r] = sacc[r];
    __syncthreads();
    if (t < 64) {
        int h = t >> 4, r = t & 15;
        float s = 0.f;
#pragma unroll
        for (int j2 = 0; j2 < 64; j2++) s += scr[(h * 64 + j2) * 16 + r];
        g_pss[js * NHEAD * NN + h * NN + i0 + r] = s;
    }
}

// ---------------- K3b: combine partials, normalize, ELU ----------------
__global__ void k3b_combine() {
    int i = blockIdx.x;
    int d = threadIdx.x;
    int h = d >> 6;
    float s = g_pss[h * NN + i] + g_pss[NHEAD * NN + h * NN + i];
    float a = g_pacc[(size_t)i * DIMF + d] + g_pacc[(size_t)NN * DIMF + i * DIMF + d];
    float o = a / s;
    o = o > 0.f ? o : expm1f(o);
    g_hcat[i * DIMF + d] = o;
}

// ---------------- K4: h2 = hcat @ W2^T and f1b/f2b ----------------
__global__ void k4_l2(const float* __restrict__ W2, const float* __restrict__ a1,
                      const float* __restrict__ a2) {
    __shared__ float W2s[NCLS][DIMF];
    __shared__ float a1s[NCLS], a2s[NCLS];
    int t = threadIdx.x;
    for (int u = t; u < NCLS * DIMF; u += 256) W2s[u >> 8][u & 255] = W2[u];
    if (t < NCLS) { a1s[t] = a1[t]; a2s[t] = a2[t]; }
    __syncthreads();

    int w = t >> 5, l = t & 31;
    int i = blockIdx.x * 8 + w;
    float hreg[8];
#pragma unroll
    for (int u = 0; u < 8; u++) hreg[u] = g_hcat[i * DIMF + l + u * 32];

    float myh2 = 0.f;
#pragma unroll
    for (int c = 0; c < NCLS; c++) {
        float s = 0.f;
#pragma unroll
        for (int u = 0; u < 8; u++) s += hreg[u] * W2s[c][l + u * 32];
#pragma unroll
        for (int o = 16; o > 0; o >>= 1) s += __shfl_xor_sync(0xffffffffu, s, o);
        if (l == c) myh2 = s;
    }
    if (l < NCLS) g_h2[i * NCLS + l] = myh2;

    float v1 = (l < NCLS) ? myh2 * a1s[l] : 0.f;
    float v2 = (l < NCLS) ? myh2 * a2s[l] : 0.f;
#pragma unroll
    for (int o = 8; o > 0; o >>= 1) {
        v1 += __shfl_xor_sync(0xffffffffu, v1, o);
        v2 += __shfl_xor_sync(0xffffffffu, v2, o);
    }
    if (l == 0) { g_f1b[i] = v1; g_f2b[i] = v2; }
}

// ---------------- K5: layer-2 attention -> logits ----------------
#define R2 16
#define CH2 64
__global__ void k5_attn2(const int* __restrict__ adj, float* __restrict__ out) {
    __shared__ float f1s[R2];
    __shared__ int   adjs[R2][CH2];
    __shared__ float f2s[CH2];
    __shared__ float ps[R2][CH2 + 1];
    __shared__ float h2s[CH2 * NCLS];
    __shared__ float ss[R2];

    int t = threadIdx.x;
    int i0 = blockIdx.x * R2;
    if (t < R2) { f1s[t] = g_f1b[i0 + t]; ss[t] = 0.f; }
    int c = t & 15, rmy = t >> 4;
    float acc = 0.f;

    for (int j0 = 0; j0 < NN; j0 += CH2) {
        __syncthreads();
#pragma unroll
        for (int u = 0; u < 4; u++) {
            int idx = t + u * 256;
            int r = idx >> 6, jj = idx & 63;
            adjs[r][jj] = adj[(i0 + r) * NN + j0 + jj];
        }
        if (t < CH2) f2s[t] = g_f2b[j0 + t];
#pragma unroll
        for (int u = 0; u < 4; u++) {
            int idx = t + u * 256;
            h2s[idx] = g_h2[j0 * NCLS + idx];
        }
        __syncthreads();
        {
            int jj = t & 63;
            int grp = t >> 6;
            float f2v = f2s[jj];
#pragma unroll
            for (int it = 0; it < 4; it++) {
                int r = grp * 4 + it;
                float z = f1s[r] + f2v;
                float e = z > 0.f ? z : 0.01f * z;
                float pv = fast_exp(e);
                ps[r][jj] = (adjs[r][jj] != 0 && e != 0.f) ? pv : 0.f;
            }
        }
        __syncthreads();
#pragma unroll 8
        for (int jj = 0; jj < CH2; jj++) {
            acc += ps[rmy][jj] * h2s[jj * NCLS + c];
        }
        if (t < R2) {
            float sp = 0.f;
#pragma unroll
            for (int jj = 0; jj < CH2; jj++) sp += ps[t][jj];
            ss[t] += sp;
        }
    }
    __syncthreads();
    out[(i0 + rmy) * NCLS + c] = acc / ss[rmy];
}

// ---------------- launcher ----------------
extern "C" void kernel_launch(void* const* d_in, const int* in_sizes, int n_in,
                              void* d_out, int out_size) {
    const float* x   = (const float*)d_in[0];
    const int*   adj = (const int*)d_in[1];
    const float* W1  = (const float*)d_in[2];
    const float* a11 = (const float*)d_in[3];
    const float* a21 = (const float*)d_in[4];
    const float* W2  = (const float*)d_in[5];
    const float* a12 = (const float*)d_in[6];
    const float* a22 = (const float*)d_in[7];
    float* out = (float*)d_out;

    k1_gemm<<<dim3(64, 4), 256>>>(x, W1);
    k2a_f1<<<NN, 256>>>(a11);
    k2b_f2<<<NN, 256>>>(a21);
    k3_attn1<<<dim3(NN / R1, JSPLIT), 256>>>(adj);   // launch #4 -> ncu captures k3
    k3b_combine<<<NN, 256>>>();
    k4_l2<<<NN / 8, 256>>>(W2, a12, a22);
    k5_attn2<<<NN / R2, 256>>>(adj, out);
}

// round 15
// speedup vs baseline: 1.7947x; 1.7947x over previous
#include <cuda_runtime.h>
#include <math.h>

#define NN 4096
#define DIMF 256
#define HIDF 64
#define NHEAD 4
#define NCLS 16
#define JSPLIT 4

// ---------------- scratch (device globals; no allocation) ----------------
__device__ float    g_h1[NN * DIMF];              // layer-1 features f32 [i][h*64+d]
__device__ unsigned g_h1t[NN * DIMF];             // layer-1 features pre-converted tf32 bits
__device__ float    g_f1a[NHEAD * NN];            // f1 per head [h][i]
__device__ float    g_f2a[NHEAD * NN];            // f2 per head [h][i]
__device__ float    g_pacc[JSPLIT * NN * DIMF];   // partial attention accumulators
__device__ float    g_pss[JSPLIT * NHEAD * NN];   // partial softmax denominators [js][h][i]
__device__ float    g_hcat[NN * DIMF];            // after attention + ELU
__device__ float    g_h2t[NCLS * NN];             // layer-2 features, transposed [c][i]
__device__ float    g_f1b[NN];
__device__ float    g_f2b[NN];

// ---------------- fast exp: FFMA/ALU only, no MUFU ----------------
__device__ __forceinline__ float fast_exp(float z) {
    z = fminf(fmaxf(z, -80.0f), 80.0f);
    float t  = z * 1.4426950408889634f;
    float tf = t + 12582912.0f;
    float fn = tf - 12582912.0f;
    float r  = t - fn;
    int   n  = __float_as_int(tf) - 0x4B400000;
    float scale = __int_as_float((n + 127) << 23);
    float p;
    p = 1.5401354e-4f;
    p = fmaf(p, r, 1.3333558e-3f);
    p = fmaf(p, r, 9.6181291e-3f);
    p = fmaf(p, r, 5.5504109e-2f);
    p = fmaf(p, r, 2.4022651e-1f);
    p = fmaf(p, r, 6.9314718e-1f);
    p = fmaf(p, r, 1.0f);
    return p * scale;
}

// ---------------- tf32 mma helpers ----------------
__device__ __forceinline__ unsigned cvt_tf32(float x) {
    unsigned r;
    asm("cvt.rna.tf32.f32 %0, %1;" : "=r"(r) : "f"(x));
    return r;
}
__device__ __forceinline__ void mma_tf32(float& c0, float& c1, float& c2, float& c3,
                                         unsigned a0, unsigned a1, unsigned a2, unsigned a3,
                                         unsigned b0, unsigned b1) {
    asm("mma.sync.aligned.m16n8k8.row.col.f32.tf32.tf32.f32 "
        "{%0,%1,%2,%3}, {%4,%5,%6,%7}, {%8,%9}, {%0,%1,%2,%3};"
        : "+f"(c0), "+f"(c1), "+f"(c2), "+f"(c3)
        : "r"(a0), "r"(a1), "r"(a2), "r"(a3), "r"(b0), "r"(b1));
}

// ---------------- K1: h1 = x @ W1^T (+ tf32 copy) ----------------
__global__ void k1_gemm(const float* __restrict__ A, const float* __restrict__ W) {
    __shared__ __align__(16) float As[16][68];
    __shared__ __align__(16) float Bs[16][68];
    int t = threadIdx.x;
    int tx = t & 15, ty = t >> 4;
    int bm = blockIdx.x * 64;
    int bn = blockIdx.y * 64;

    float acc[4][4];
#pragma unroll
    for (int i = 0; i < 4; i++)
#pragma unroll
        for (int j = 0; j < 4; j++) acc[i][j] = 0.f;

    int lr = t >> 2;
    int lk = (t & 3) * 4;

    for (int k0 = 0; k0 < DIMF; k0 += 16) {
        float4 av = *(const float4*)(A + (bm + lr) * DIMF + k0 + lk);
        float4 bv = *(const float4*)(W + (bn + lr) * DIMF + k0 + lk);
        As[lk + 0][lr] = av.x; As[lk + 1][lr] = av.y;
        As[lk + 2][lr] = av.z; As[lk + 3][lr] = av.w;
        Bs[lk + 0][lr] = bv.x; Bs[lk + 1][lr] = bv.y;
        Bs[lk + 2][lr] = bv.z; Bs[lk + 3][lr] = bv.w;
        __syncthreads();
#pragma unroll
        for (int k = 0; k < 16; k++) {
            float4 a4 = *(const float4*)&As[k][ty * 4];
            float4 b4 = *(const float4*)&Bs[k][tx * 4];
            float a[4] = {a4.x, a4.y, a4.z, a4.w};
            float b[4] = {b4.x, b4.y, b4.z, b4.w};
#pragma unroll
            for (int i = 0; i < 4; i++)
#pragma unroll
                for (int j = 0; j < 4; j++) acc[i][j] += a[i] * b[j];
        }
        __syncthreads();
    }
#pragma unroll
    for (int i = 0; i < 4; i++) {
        float4 o = make_float4(acc[i][0], acc[i][1], acc[i][2], acc[i][3]);
        *(float4*)&g_h1[(bm + ty * 4 + i) * DIMF + bn + tx * 4] = o;
        uint4 ot;
        ot.x = cvt_tf32(acc[i][0]); ot.y = cvt_tf32(acc[i][1]);
        ot.z = cvt_tf32(acc[i][2]); ot.w = cvt_tf32(acc[i][3]);
        *(uint4*)&g_h1t[(bm + ty * 4 + i) * DIMF + bn + tx * 4] = ot;
    }
}

// ---------------- K2a/K2b: f1 / f2 per head ----------------
__global__ void k2a_f1(const float* __restrict__ a1) {
    __shared__ float s1[256];
    int i = blockIdx.x;
    int t = threadIdx.x;
    s1[t] = g_h1[i * DIMF + t] * a1[t];
    __syncthreads();
    for (int st = 32; st > 0; st >>= 1) {
        if ((t & 63) < st) s1[t] += s1[t + st];
        __syncthreads();
    }
    if ((t & 63) == 0) g_f1a[(t >> 6) * NN + i] = s1[t];
}
__global__ void k2b_f2(const float* __restrict__ a2) {
    __shared__ float s2[256];
    int i = blockIdx.x;
    int t = threadIdx.x;
    s2[t] = g_h1[i * DIMF + t] * a2[t];
    __syncthreads();
    for (int st = 32; st > 0; st >>= 1) {
        if ((t & 63) < st) s2[t] += s2[t + st];
        __syncthreads();
    }
    if ((t & 63) == 0) g_f2a[(t >> 6) * NN + i] = s2[t];
}

// ---------------- K3: layer-1 attention, tf32 MMA with smem-staged B ------
// grid (NN/R1, JSPLIT), 256 threads (8 warps).
// Per chunk (64 j): exp phase -> psu (tf32 P); then 4 stages of 16 j-rows:
//   stage Hs (coalesced LDG.128 from g_h1t, XOR-swizzled STS) -> mma 2 k-groups.
#define R1 16
#define CH1 64
#define JCHUNKS (NN / JSPLIT / CH1)   // 16
__global__ __launch_bounds__(256, 3) void k3_attn1(const int* __restrict__ adj) {
    __shared__ float    f1s[R1][NHEAD];
    __shared__ int      adjs[R1][CH1];
    __shared__ float    f2s[NHEAD][CH1];
    __shared__ unsigned psu[NHEAD][R1][68];   // tf32 P bits, stride 68
    __shared__ unsigned Hs[16][256];          // tf32 H bits, 16 rows, swizzled

    int t = threadIdx.x;
    int i0 = blockIdx.x * R1;
    int js = blockIdx.y;
    int jbase = js * (NN / JSPLIT);

    if (t < R1 * NHEAD) {
        int r = t >> 2, h = t & 3;
        f1s[r][h] = g_f1a[h * NN + i0 + r];
    }

    const int jj   = t & 63;
    const int hh   = t >> 6;
    const int w    = t >> 5;
    const int lane = t & 31;
    const int gid  = lane >> 2;       // 0..7
    const int tig  = lane & 3;        // 0..3
    const int head = w >> 1;
    const int dbase = w * 32;

    float acc[4][4];
#pragma unroll
    for (int nt = 0; nt < 4; nt++)
#pragma unroll
        for (int c = 0; c < 4; c++) acc[nt][c] = 0.f;

    float sacc[R1];
#pragma unroll
    for (int r = 0; r < R1; r++) sacc[r] = 0.f;

    for (int c = 0; c < JCHUNKS; c++) {
        int j0 = jbase + c * CH1;
        __syncthreads();
        // adjacency chunk 16x64
#pragma unroll
        for (int u = 0; u < 4; u++) {
            int idx = t + u * 256;
            int r = idx >> 6, j2 = idx & 63;
            adjs[r][j2] = adj[(i0 + r) * NN + j0 + j2];
        }
        f2s[hh][jj] = g_f2a[hh * NN + j0 + jj];
        __syncthreads();
        // exp phase: P tf32 bits to smem, f32 denominator in regs
        {
            float f2v = f2s[hh][jj];
#pragma unroll
            for (int r = 0; r < R1; r++) {
                float z = f1s[r][hh] + f2v;
                float e = z > 0.f ? z : 0.01f * z;
                float pv = fast_exp(e);
                float p = (adjs[r][jj] != 0 && e != 0.f) ? pv : 0.f;
                psu[hh][r][jj] = cvt_tf32(p);
                sacc[r] += p;
            }
        }
        // 4 stages of 16 j-rows each
#pragma unroll 1
        for (int s = 0; s < 4; s++) {
            __syncthreads();   // protects Hs (prev readers) and psu (stage 0: exp writes)
            // stage 16 rows of H (tf32 bits), coalesced, swizzled
#pragma unroll
            for (int u = 0; u < 4; u++) {
                int f4  = u * 256 + t;         // 0..1023
                int row = f4 >> 6;             // 0..15
                int col = (f4 & 63) * 4;
                uint4 v = *(const uint4*)&g_h1t[(j0 + s * 16 + row) * DIMF + col];
                *(uint4*)&Hs[row][col ^ ((row & 3) * 8)] = v;
            }
            __syncthreads();
            // mma: 2 k-groups of 8 within this stage
#pragma unroll
            for (int kk = 0; kk < 2; kk++) {
                int colA = (s * 2 + kk) * 8 + tig;
                unsigned a0 = psu[head][gid][colA];
                unsigned a1 = psu[head][gid + 8][colA];
                unsigned a2 = psu[head][gid][colA + 4];
                unsigned a3 = psu[head][gid + 8][colA + 4];
                int rb = kk * 8 + tig;
                int sw = tig * 8;
#pragma unroll
                for (int nt = 0; nt < 4; nt++) {
                    int dcol = dbase + nt * 8 + gid;
                    unsigned b0 = Hs[rb][dcol ^ sw];
                    unsigned b1 = Hs[rb + 4][dcol ^ sw];
                    mma_tf32(acc[nt][0], acc[nt][1], acc[nt][2], acc[nt][3],
                             a0, a1, a2, a3, b0, b1);
                }
            }
        }
    }

    // store accumulators
#pragma unroll
    for (int nt = 0; nt < 4; nt++) {
        int col = dbase + nt * 8 + tig * 2;
        float2 lohi0 = make_float2(acc[nt][0], acc[nt][1]);
        float2 lohi1 = make_float2(acc[nt][2], acc[nt][3]);
        *(float2*)&g_pacc[(size_t)js * NN * DIMF + (i0 + gid) * DIMF + col]     = lohi0;
        *(float2*)&g_pacc[(size_t)js * NN * DIMF + (i0 + gid + 8) * DIMF + col] = lohi1;
    }

    // reduce sacc over 64 jj-lanes per head (reuse psu as scratch: 16KB <= 17.4KB)
    __syncthreads();
    float* scr = (float*)psu;
#pragma unroll
    for (int r = 0; r < R1; r++) scr[t * 16 + r] = sacc[r];
    __syncthreads();
    if (t < 64) {
        int h = t >> 4, r = t & 15;
        float s = 0.f;
#pragma unroll
        for (int j2 = 0; j2 < 64; j2++) s += scr[(h * 64 + j2) * 16 + r];
        g_pss[js * NHEAD * NN + h * NN + i0 + r] = s;
    }
}

// ---------------- K3b: combine partials, normalize, ELU ----------------
__global__ void k3b_combine() {
    int i = blockIdx.x;
    int d = threadIdx.x;
    int h = d >> 6;
    float s = 0.f, a = 0.f;
#pragma unroll
    for (int js = 0; js < JSPLIT; js++) {
        s += g_pss[js * NHEAD * NN + h * NN + i];
        a += g_pacc[(size_t)js * NN * DIMF + i * DIMF + d];
    }
    float o = a / s;
    o = o > 0.f ? o : expm1f(o);
    g_hcat[i * DIMF + d] = o;
}

// ---------------- K4: h2t = (hcat @ W2^T)^T and f1b/f2b ----------------
__global__ void k4_l2(const float* __restrict__ W2, const float* __restrict__ a1,
                      const float* __restrict__ a2) {
    __shared__ float W2s[NCLS][DIMF];
    __shared__ float a1s[NCLS], a2s[NCLS];
    int t = threadIdx.x;
    for (int u = t; u < NCLS * DIMF; u += 256) W2s[u >> 8][u & 255] = W2[u];
    if (t < NCLS) { a1s[t] = a1[t]; a2s[t] = a2[t]; }
    __syncthreads();

    int w = t >> 5, l = t & 31;
    int i = blockIdx.x * 8 + w;
    float hreg[8];
#pragma unroll
    for (int u = 0; u < 8; u++) hreg[u] = g_hcat[i * DIMF + l + u * 32];

    float myh2 = 0.f;
#pragma unroll
    for (int c = 0; c < NCLS; c++) {
        float s = 0.f;
#pragma unroll
        for (int u = 0; u < 8; u++) s += hreg[u] * W2s[c][l + u * 32];
#pragma unroll
        for (int o = 16; o > 0; o >>= 1) s += __shfl_xor_sync(0xffffffffu, s, o);
        if (l == c) myh2 = s;
    }
    if (l < NCLS) g_h2t[l * NN + i] = myh2;   // transposed layout [c][i]

    float v1 = (l < NCLS) ? myh2 * a1s[l] : 0.f;
    float v2 = (l < NCLS) ? myh2 * a2s[l] : 0.f;
#pragma unroll
    for (int o = 8; o > 0; o >>= 1) {
        v1 += __shfl_xor_sync(0xffffffffu, v1, o);
        v2 += __shfl_xor_sync(0xffffffffu, v2, o);
    }
    if (l == 0) { g_f1b[i] = v1; g_f2b[i] = v2; }
}

// ---------------- K5: layer-2 attention -> logits ----------------
#define R2 16
#define CH2 64
__global__ void k5_attn2(const int* __restrict__ adj, float* __restrict__ out) {
    __shared__ float f1s[R2];
    __shared__ int   adjs[R2][CH2];                 // reused as scr at end (4KB)
    __shared__ float f2s[CH2];
    __shared__ __align__(16) float ps[R2][68];
    __shared__ __align__(16) float h2st[NCLS][68];
    __shared__ float ss[R2];

    int t = threadIdx.x;
    int i0 = blockIdx.x * R2;
    if (t < R2) f1s[t] = g_f1b[i0 + t];
    const int c   = t & 15, rmy = t >> 4;
    const int jj  = t & 63, grp = t >> 6;
    float acc = 0.f;
    float sacc[4] = {0.f, 0.f, 0.f, 0.f};

    for (int j0 = 0; j0 < NN; j0 += CH2) {
        __syncthreads();
#pragma unroll
        for (int u = 0; u < 4; u++) {
            int idx = t + u * 256;
            adjs[idx >> 6][idx & 63] = adj[(i0 + (idx >> 6)) * NN + j0 + (idx & 63)];
        }
        if (t < CH2) f2s[t] = g_f2b[j0 + t];
#pragma unroll
        for (int u = 0; u < 4; u++) {
            int idx = t + u * 256;
            int cc = idx >> 6, j2 = idx & 63;
            h2st[cc][j2] = g_h2t[cc * NN + j0 + j2];
        }
        __syncthreads();
        {
            float f2v = f2s[jj];
#pragma unroll
            for (int it = 0; it < 4; it++) {
                int r = grp * 4 + it;
                float z = f1s[r] + f2v;
                float e = z > 0.f ? z : 0.01f * z;
                float pv = fast_exp(e);
                float p = (adjs[r][jj] != 0 && e != 0.f) ? pv : 0.f;
                ps[r][jj] = p;
                sacc[it] += p;
            }
        }
        __syncthreads();
#pragma unroll
        for (int q = 0; q < 16; q++) {
            float4 pq = *(const float4*)&ps[rmy][q * 4];
            float4 hq = *(const float4*)&h2st[c][q * 4];
            acc += pq.x * hq.x;
            acc += pq.y * hq.y;
            acc += pq.z * hq.z;
            acc += pq.w * hq.w;
        }
    }
    // final denominator reduction (reuse adjs as float scratch)
    __syncthreads();
    float* scr = (float*)adjs;
#pragma unroll
    for (int it = 0; it < 4; it++) scr[t * 4 + it] = sacc[it];
    __syncthreads();
    if (t < R2) {
        int g = t >> 2, it = t & 3;
        float s = 0.f;
#pragma unroll
        for (int j2 = 0; j2 < 64; j2++) s += scr[(g * 64 + j2) * 4 + it];
        ss[t] = s;
    }
    __syncthreads();
    out[(i0 + rmy) * NCLS + c] = acc / ss[rmy];
}

// ---------------- launcher ----------------
extern "C" void kernel_launch(void* const* d_in, const int* in_sizes, int n_in,
                              void* d_out, int out_size) {
    const float* x   = (const float*)d_in[0];
    const int*   adj = (const int*)d_in[1];
    const float* W1  = (const float*)d_in[2];
    const float* a11 = (const float*)d_in[3];
    const float* a21 = (const float*)d_in[4];
    const float* W2  = (const float*)d_in[5];
    const float* a12 = (const float*)d_in[6];
    const float* a22 = (const float*)d_in[7];
    float* out = (float*)d_out;

    k1_gemm<<<dim3(64, 4), 256>>>(x, W1);
    k2a_f1<<<NN, 256>>>(a11);
    k2b_f2<<<NN, 256>>>(a21);
    k3_attn1<<<dim3(NN / R1, JSPLIT), 256>>>(adj);   // launch #4 -> ncu captures k3
    k3b_combine<<<NN, 256>>>();
    k4_l2<<<NN / 8, 256>>>(W2, a12, a22);
    k5_attn2<<<NN / R2, 256>>>(adj, out);
}

// round 17
// speedup vs baseline: 1.8706x; 1.0423x over previous
#include <cuda_runtime.h>
#include <math.h>

#define NN 4096
#define DIMF 256
#define HIDF 64
#define NHEAD 4
#define NCLS 16
#define JSPLIT 4

// ---------------- scratch (device globals; no allocation) ----------------
__device__ float    g_h1[NN * DIMF];              // layer-1 features f32 [i][h*64+d]
__device__ uint2    g_h1p[(NN / 2) * DIMF];       // tf32 pairs: slot (jb*4+s)*256+d = (H[jb*8+s][d], H[jb*8+s+4][d])
__device__ float    g_f1a[NHEAD * NN];            // f1 per head [h][i]
__device__ float    g_f2a[NHEAD * NN];            // f2 per head [h][i]
__device__ float    g_pacc[JSPLIT * NN * DIMF];   // partial attention accumulators
__device__ float    g_pss[JSPLIT * NHEAD * NN];   // partial softmax denominators [js][h][i]
__device__ float    g_hcat[NN * DIMF];            // after attention + ELU
__device__ float    g_h2t[NCLS * NN];             // layer-2 features, transposed [c][i]
__device__ float    g_f1b[NN];
__device__ float    g_f2b[NN];

// ---------------- fast exp: FFMA/ALU only, no MUFU ----------------
__device__ __forceinline__ float fast_exp(float z) {
    z = fminf(fmaxf(z, -80.0f), 80.0f);
    float t  = z * 1.4426950408889634f;
    float tf = t + 12582912.0f;
    float fn = tf - 12582912.0f;
    float r  = t - fn;
    int   n  = __float_as_int(tf) - 0x4B400000;
    float scale = __int_as_float((n + 127) << 23);
    float p;
    p = 1.5401354e-4f;
    p = fmaf(p, r, 1.3333558e-3f);
    p = fmaf(p, r, 9.6181291e-3f);
    p = fmaf(p, r, 5.5504109e-2f);
    p = fmaf(p, r, 2.4022651e-1f);
    p = fmaf(p, r, 6.9314718e-1f);
    p = fmaf(p, r, 1.0f);
    return p * scale;
}

// ---------------- tf32 mma helpers ----------------
__device__ __forceinline__ unsigned cvt_tf32(float x) {
    unsigned r;
    asm("cvt.rna.tf32.f32 %0, %1;" : "=r"(r) : "f"(x));
    return r;
}
__device__ __forceinline__ void mma_tf32(float& c0, float& c1, float& c2, float& c3,
                                         unsigned a0, unsigned a1, unsigned a2, unsigned a3,
                                         unsigned b0, unsigned b1) {
    asm("mma.sync.aligned.m16n8k8.row.col.f32.tf32.tf32.f32 "
        "{%0,%1,%2,%3}, {%4,%5,%6,%7}, {%8,%9}, {%0,%1,%2,%3};"
        : "+f"(c0), "+f"(c1), "+f"(c2), "+f"(c3)
        : "r"(a0), "r"(a1), "r"(a2), "r"(a3), "r"(b0), "r"(b1));
}

// ---------------- K1: h1 = x @ W1^T ----------------
__global__ void k1_gemm(const float* __restrict__ A, const float* __restrict__ W) {
    __shared__ __align__(16) float As[16][68];
    __shared__ __align__(16) float Bs[16][68];
    int t = threadIdx.x;
    int tx = t & 15, ty = t >> 4;
    int bm = blockIdx.x * 64;
    int bn = blockIdx.y * 64;

    float acc[4][4];
#pragma unroll
    for (int i = 0; i < 4; i++)
#pragma unroll
        for (int j = 0; j < 4; j++) acc[i][j] = 0.f;

    int lr = t >> 2;
    int lk = (t & 3) * 4;

    for (int k0 = 0; k0 < DIMF; k0 += 16) {
        float4 av = *(const float4*)(A + (bm + lr) * DIMF + k0 + lk);
        float4 bv = *(const float4*)(W + (bn + lr) * DIMF + k0 + lk);
        As[lk + 0][lr] = av.x; As[lk + 1][lr] = av.y;
        As[lk + 2][lr] = av.z; As[lk + 3][lr] = av.w;
        Bs[lk + 0][lr] = bv.x; Bs[lk + 1][lr] = bv.y;
        Bs[lk + 2][lr] = bv.z; Bs[lk + 3][lr] = bv.w;
        __syncthreads();
#pragma unroll
        for (int k = 0; k < 16; k++) {
            float4 a4 = *(const float4*)&As[k][ty * 4];
            float4 b4 = *(const float4*)&Bs[k][tx * 4];
            float a[4] = {a4.x, a4.y, a4.z, a4.w};
            float b[4] = {b4.x, b4.y, b4.z, b4.w};
#pragma unroll
            for (int i = 0; i < 4; i++)
#pragma unroll
                for (int j = 0; j < 4; j++) acc[i][j] += a[i] * b[j];
        }
        __syncthreads();
    }
#pragma unroll
    for (int i = 0; i < 4; i++) {
        float4 o = make_float4(acc[i][0], acc[i][1], acc[i][2], acc[i][3]);
        *(float4*)&g_h1[(bm + ty * 4 + i) * DIMF + bn + tx * 4] = o;
    }
}

// ---------------- K1b: pack H into tf32 mma-fragment pairs ----------------
// block b in [0,2048): jb=b>>2, s=b&3. Writes uint2 (tf32(H[jb*8+s][d]), tf32(H[jb*8+s+4][d])).
__global__ void k1b_pack() {
    int b = blockIdx.x;
    int d = threadIdx.x;
    int jlo = (b >> 2) * 8 + (b & 3);
    uint2 v;
    v.x = cvt_tf32(g_h1[jlo * DIMF + d]);
    v.y = cvt_tf32(g_h1[(jlo + 4) * DIMF + d]);
    g_h1p[b * DIMF + d] = v;
}

// ---------------- K2: f1/f2 per head ----------------
__global__ void k2_f(const float* __restrict__ a1, const float* __restrict__ a2) {
    __shared__ float s1[256], s2[256];
    int i = blockIdx.x;
    int t = threadIdx.x;
    float h = g_h1[i * DIMF + t];
    s1[t] = h * a1[t];
    s2[t] = h * a2[t];
    __syncthreads();
    for (int st = 32; st > 0; st >>= 1) {
        if ((t & 63) < st) { s1[t] += s1[t + st]; s2[t] += s2[t + st]; }
        __syncthreads();
    }
    if ((t & 63) == 0) {
        int hh = t >> 6;
        g_f1a[hh * NN + i] = s1[t];
        g_f2a[hh * NN + i] = s2[t];
    }
}

// ---------------- K3: layer-1 attention, tf32 MMA, direct-gmem B ---------
// grid (NN/R1, JSPLIT), 256 threads (8 warps).
// exp phase: thread (hh=t>>6, r=(t>>2)&15, g=t&3) computes p for 16 jj in [g*16,g*16+16).
// MMA phase: warp w (d-slice w*32), head=w>>1; A frags from psu (smem), B via LDG.64 from g_h1p.
#define R1 16
#define CH1 64
#define JCHUNKS (NN / JSPLIT / CH1)   // 16
__global__ __launch_bounds__(256, 3) void k3_attn1(const int* __restrict__ adj) {
    __shared__ float    f1s[R1][NHEAD];
    __shared__ int      adjs[R1][CH1];
    __shared__ float    f2s[NHEAD][CH1];
    __shared__ __align__(16) unsigned psu[NHEAD][R1][68];   // tf32 P bits

    int t = threadIdx.x;
    int i0 = blockIdx.x * R1;
    int js = blockIdx.y;
    int jbase = js * (NN / JSPLIT);

    if (t < R1 * NHEAD) {
        int r = t >> 2, h = t & 3;
        f1s[r][h] = g_f1a[h * NN + i0 + r];
    }
    __syncthreads();

    // exp-phase identity
    const int ehh = t >> 6;
    const int er  = (t >> 2) & 15;
    const int eg  = t & 3;
    const float f1v = f1s[er][ehh];

    // mma-phase identity
    const int w    = t >> 5;
    const int lane = t & 31;
    const int gid  = lane >> 2;
    const int tig  = lane & 3;
    const int head = w >> 1;
    const int dbase = w * 32;

    float acc[4][4];
#pragma unroll
    for (int nt = 0; nt < 4; nt++)
#pragma unroll
        for (int c = 0; c < 4; c++) acc[nt][c] = 0.f;
    float sacc = 0.f;

    // staging identity: 1 int4 of adj per thread
    const int srow = t >> 4;            // 0..15
    const int scol = (t & 15) * 4;      // 0..60

    for (int c = 0; c < JCHUNKS; c++) {
        int j0 = jbase + c * CH1;
        __syncthreads();   // psu/adjs free (prev chunk consumed)
        // stage adj (16x64 ints, one int4/thread) and f2 (4x64, one float/thread)
        {
            int4 av = *(const int4*)&adj[(i0 + srow) * NN + j0 + scol];
            *(int4*)&adjs[srow][scol] = av;
            f2s[t >> 6][t & 63] = g_f2a[(t >> 6) * NN + j0 + (t & 63)];
        }
        __syncthreads();
        // exp phase: 16 p's per thread, vectorized smem I/O
#pragma unroll
        for (int u = 0; u < 4; u++) {
            int jq = eg * 16 + u * 4;
            int4   a4 = *(const int4*)&adjs[er][jq];
            float4 f4 = *(const float4*)&f2s[ehh][jq];
            float pr[4];
            float fv[4] = {f4.x, f4.y, f4.z, f4.w};
            int   ad[4] = {a4.x, a4.y, a4.z, a4.w};
#pragma unroll
            for (int q = 0; q < 4; q++) {
                float z = f1v + fv[q];
                float e = z > 0.f ? z : 0.01f * z;
                float pv = fast_exp(e);
                float p = (ad[q] != 0 && e != 0.f) ? pv : 0.f;
                pr[q] = p;
                sacc += p;
            }
            uint4 pb;
            pb.x = cvt_tf32(pr[0]); pb.y = cvt_tf32(pr[1]);
            pb.z = cvt_tf32(pr[2]); pb.w = cvt_tf32(pr[3]);
            *(uint4*)&psu[ehh][er][jq] = pb;
        }
        __syncthreads();
        // MMA phase: 8 k-groups, A from psu, B from g_h1p (L1-resident)
        const uint2* __restrict__ hp = &g_h1p[((j0 >> 3) * 4 + tig) * DIMF];
#pragma unroll
        for (int kk = 0; kk < 8; kk++) {
            int colA = kk * 8 + tig;
            unsigned a0 = psu[head][gid][colA];
            unsigned a1 = psu[head][gid + 8][colA];
            unsigned a2 = psu[head][gid][colA + 4];
            unsigned a3 = psu[head][gid + 8][colA + 4];
            const uint2* hpk = hp + kk * 4 * DIMF;
#pragma unroll
            for (int nt = 0; nt < 4; nt++) {
                int dcol = dbase + nt * 8 + gid;
                uint2 b = __ldg(&hpk[dcol]);
                mma_tf32(acc[nt][0], acc[nt][1], acc[nt][2], acc[nt][3],
                         a0, a1, a2, a3, b.x, b.y);
            }
        }
    }

    // store accumulators
#pragma unroll
    for (int nt = 0; nt < 4; nt++) {
        int col = dbase + nt * 8 + tig * 2;
        float2 lohi0 = make_float2(acc[nt][0], acc[nt][1]);
        float2 lohi1 = make_float2(acc[nt][2], acc[nt][3]);
        *(float2*)&g_pacc[(size_t)js * NN * DIMF + (i0 + gid) * DIMF + col]     = lohi0;
        *(float2*)&g_pacc[(size_t)js * NN * DIMF + (i0 + gid + 8) * DIMF + col] = lohi1;
    }

    // softmax denominator: reduce sacc over the 4 jj-quarter lanes (adjacent threads)
    sacc += __shfl_xor_sync(0xffffffffu, sacc, 1);
    sacc += __shfl_xor_sync(0xffffffffu, sacc, 2);
    if (eg == 0)
        g_pss[js * NHEAD * NN + ehh * NN + i0 + er] = sacc;
}

// ---------------- K3b: combine partials, normalize, ELU ----------------
__global__ void k3b_combine() {
    int i = blockIdx.x;
    int d = threadIdx.x;
    int h = d >> 6;
    float s = 0.f, a = 0.f;
#pragma unroll
    for (int js = 0; js < JSPLIT; js++) {
        s += g_pss[js * NHEAD * NN + h * NN + i];
        a += g_pacc[(size_t)js * NN * DIMF + i * DIMF + d];
    }
    float o = a / s;
    o = o > 0.f ? o : expm1f(o);
    g_hcat[i * DIMF + d] = o;
}

// ---------------- K4: h2t = (hcat @ W2^T)^T and f1b/f2b ----------------
__global__ void k4_l2(const float* __restrict__ W2, const float* __restrict__ a1,
                      const float* __restrict__ a2) {
    __shared__ float W2s[NCLS][DIMF];
    __shared__ float a1s[NCLS], a2s[NCLS];
    int t = threadIdx.x;
    for (int u = t; u < NCLS * DIMF; u += 256) W2s[u >> 8][u & 255] = W2[u];
    if (t < NCLS) { a1s[t] = a1[t]; a2s[t] = a2[t]; }
    __syncthreads();

    int w = t >> 5, l = t & 31;
    int i = blockIdx.x * 8 + w;
    float hreg[8];
#pragma unroll
    for (int u = 0; u < 8; u++) hreg[u] = g_hcat[i * DIMF + l + u * 32];

    float myh2 = 0.f;
#pragma unroll
    for (int c = 0; c < NCLS; c++) {
        float s = 0.f;
#pragma unroll
        for (int u = 0; u < 8; u++) s += hreg[u] * W2s[c][l + u * 32];
#pragma unroll
        for (int o = 16; o > 0; o >>= 1) s += __shfl_xor_sync(0xffffffffu, s, o);
        if (l == c) myh2 = s;
    }
    if (l < NCLS) g_h2t[l * NN + i] = myh2;

    float v1 = (l < NCLS) ? myh2 * a1s[l] : 0.f;
    float v2 = (l < NCLS) ? myh2 * a2s[l] : 0.f;
#pragma unroll
    for (int o = 8; o > 0; o >>= 1) {
        v1 += __shfl_xor_sync(0xffffffffu, v1, o);
        v2 += __shfl_xor_sync(0xffffffffu, v2, o);
    }
    if (l == 0) { g_f1b[i] = v1; g_f2b[i] = v2; }
}

// ---------------- K5: layer-2 attention -> logits ----------------
#define R2 16
#define CH2 64
__global__ void k5_attn2(const int* __restrict__ adj, float* __restrict__ out) {
    __shared__ float f1s[R2];
    __shared__ int   adjs[R2][CH2];                 // reused as scr at end (4KB)
    __shared__ float f2s[CH2];
    __shared__ __align__(16) float ps[R2][68];
    __shared__ __align__(16) float h2st[NCLS][68];
    __shared__ float ss[R2];

    int t = threadIdx.x;
    int i0 = blockIdx.x * R2;
    if (t < R2) f1s[t] = g_f1b[i0 + t];
    const int c   = t & 15, rmy = t >> 4;
    const int jj  = t & 63, grp = t >> 6;
    float acc = 0.f;
    float sacc[4] = {0.f, 0.f, 0.f, 0.f};

    for (int j0 = 0; j0 < NN; j0 += CH2) {
        __syncthreads();
#pragma unroll
        for (int u = 0; u < 4; u++) {
            int idx = t + u * 256;
            adjs[idx >> 6][idx & 63] = adj[(i0 + (idx >> 6)) * NN + j0 + (idx & 63)];
        }
        if (t < CH2) f2s[t] = g_f2b[j0 + t];
#pragma unroll
        for (int u = 0; u < 4; u++) {
            int idx = t + u * 256;
            int cc = idx >> 6, j2 = idx & 63;
            h2st[cc][j2] = g_h2t[cc * NN + j0 + j2];
        }
        __syncthreads();
        {
            float f2v = f2s[jj];
#pragma unroll
            for (int it = 0; it < 4; it++) {
                int r = grp * 4 + it;
                float z = f1s[r] + f2v;
                float e = z > 0.f ? z : 0.01f * z;
                float pv = fast_exp(e);
                float p = (adjs[r][jj] != 0 && e != 0.f) ? pv : 0.f;
                ps[r][jj] = p;
                sacc[it] += p;
            }
        }
        __syncthreads();
#pragma unroll
        for (int q = 0; q < 16; q++) {
            float4 pq = *(const float4*)&ps[rmy][q * 4];
            float4 hq = *(const float4*)&h2st[c][q * 4];
            acc += pq.x * hq.x;
            acc += pq.y * hq.y;
            acc += pq.z * hq.z;
            acc += pq.w * hq.w;
        }
    }
    __syncthreads();
    float* scr = (float*)adjs;
#pragma unroll
    for (int it = 0; it < 4; it++) scr[t * 4 + it] = sacc[it];
    __syncthreads();
    if (t < R2) {
        int g = t >> 2, it = t & 3;
        float s = 0.f;
#pragma unroll
        for (int j2 = 0; j2 < 64; j2++) s += scr[(g * 64 + j2) * 4 + it];
        ss[t] = s;
    }
    __syncthreads();
    out[(i0 + rmy) * NCLS + c] = acc / ss[rmy];
}

// ---------------- launcher ----------------
extern "C" void kernel_launch(void* const* d_in, const int* in_sizes, int n_in,
                              void* d_out, int out_size) {
    const float* x   = (const float*)d_in[0];
    const int*   adj = (const int*)d_in[1];
    const float* W1  = (const float*)d_in[2];
    const float* a11 = (const float*)d_in[3];
    const float* a21 = (const float*)d_in[4];
    const float* W2  = (const float*)d_in[5];
    const float* a12 = (const float*)d_in[6];
    const float* a22 = (const float*)d_in[7];
    float* out = (float*)d_out;

    k1_gemm<<<dim3(64, 4), 256>>>(x, W1);
    k1b_pack<<<NN / 2, 256>>>();
    k2_f<<<NN, 256>>>(a11, a21);
    k3_attn1<<<dim3(NN / R1, JSPLIT), 256>>>(adj);   // launch #4 -> ncu captures k3
    k3b_combine<<<NN, 256>>>();
    k4_l2<<<NN / 8, 256>>>(W2, a12, a22);
    k5_attn2<<<NN / R2, 256>>>(adj, out);
}